// round 8
// baseline (speedup 1.0000x reference)
#include <cuda_runtime.h>
#include <cstdint>

// ============================================================================
// Problem dims (fixed by the dataset)
// ============================================================================
#define B_DIM 256
#define P_DIM 64
#define Q_DIM 128
#define C_DIM 1000
#define F_DIM 2048

// ============================================================================
// Config
// ============================================================================
static constexpr int THREADS    = 512;           // 16 warps: 4 (m) x 4 (n)
static constexpr int KT         = 32;            // k-elems (fp32) per stage
static constexpr int NSTAGES    = F_DIM / KT;    // 64
static constexpr int NBUF       = 3;             // cp.async pipeline depth
static constexpr int TILE_BYTES = 128 * KT * 4;  // 16384 (A or B tile)
static constexpr int STAGE_BYTES = 2 * TILE_BYTES;   // 32768

// smem layout (bytes). Tile triple-buffer [0, 98304) is reused as the logits
// matrix (128 x 129 fp32, padded stride to dodge bank conflicts) post-GEMM.
static constexpr int LOGIT_STRIDE = 129;
static constexpr int SM_LOGITS = 0;                        // 66048 bytes used
static constexpr int SM_BIAS   = NBUF * STAGE_BYTES;       // 98304: 128 f32
static constexpr int SM_LSE    = SM_BIAS + 512;            // 128 f32
static constexpr int SM_PMAX   = SM_LSE + 512;             // 512 f32
static constexpr int SM_PSUM   = SM_PMAX + 2048;           // 512 f32
static constexpr int SM_IDX    = SM_PSUM + 2048;           // 1000 i32 (4000 B)
static constexpr int SM_FLAG   = SM_IDX + 4000;            // 1 i32 (i64 flag)
static constexpr int SM_TOTAL  = SM_IDX + 4096;            // 107008

// ============================================================================
// Helpers
// ============================================================================
__device__ __forceinline__ uint32_t smem_to_u32(const void* smem_ptr) {
    uint32_t addr;
    asm("{ .reg .u64 tmp; cvta.to.shared.u64 tmp, %1; cvt.u32.u64 %0, tmp; }"
        : "=r"(addr) : "l"(smem_ptr));
    return addr;
}

__device__ __forceinline__ uint32_t f2tf32(float f) {
    uint32_t u;
    asm("cvt.rna.tf32.f32 %0, %1;" : "=r"(u) : "f"(f));
    return u;
}

__device__ __forceinline__ void mma_tf32(float* c, const uint32_t* a, const uint32_t* b) {
    asm volatile(
        "mma.sync.aligned.m16n8k8.row.col.f32.tf32.tf32.f32 "
        "{%0,%1,%2,%3}, {%4,%5,%6,%7}, {%8,%9}, {%0,%1,%2,%3};"
        : "+f"(c[0]), "+f"(c[1]), "+f"(c[2]), "+f"(c[3])
        : "r"(a[0]), "r"(a[1]), "r"(a[2]), "r"(a[3]), "r"(b[0]), "r"(b[1]));
}

#define CP_ASYNC_16(dst_u32, src_sz) \
    asm volatile("cp.async.cg.shared.global [%0], [%1], 16;" \
                 :: "r"(dst_u32), "l"(src_sz) : "memory")
#define CP_ASYNC_COMMIT() asm volatile("cp.async.commit_group;" ::: "memory")
#define CP_ASYNC_WAIT(n)  asm volatile("cp.async.wait_group %0;" :: "n"(n) : "memory")

// ============================================================================
// Fused kernel: tf32 mma.sync GEMM (128x128x2048) + bias + log_softmax + gather
//   grid = (2 m-tiles of 128 batch rows, 64 partitions), 16 warps/CTA
// ============================================================================
__global__ void __launch_bounds__(THREADS, 1)
combinatorial_classifier_kernel(
    const float* __restrict__ x,            // [B, F]
    const float* __restrict__ W,            // [P*Q, F] (K contiguous)
    const float* __restrict__ bias,         // [P, Q]
    const void*  __restrict__ part_idx,     // [P, C] int32 OR int64 (detected)
    float* __restrict__ out)                // [B, P, C]
{
    extern __shared__ char smem[];
    const uint32_t su  = smem_to_u32(smem);
    const int tid      = threadIdx.x;
    const int wid      = tid >> 5;
    const int lid      = tid & 31;
    const int m_tile   = blockIdx.x;          // 0..1
    const int p        = blockIdx.y;          // 0..63
    const int warp_m   = wid >> 2;            // 0..3  -> 32 rows each
    const int warp_n   = wid & 3;             // 0..3  -> 32 cols each
    const int g        = lid >> 2;            // 0..7
    const int tg       = lid & 3;             // 0..3

    float* logits_s = reinterpret_cast<float*>(smem + SM_LOGITS);
    float* bias_s   = reinterpret_cast<float*>(smem + SM_BIAS);
    float* lse_s    = reinterpret_cast<float*>(smem + SM_LSE);
    float* pmax_s   = reinterpret_cast<float*>(smem + SM_PMAX);
    float* psum_s   = reinterpret_cast<float*>(smem + SM_PSUM);
    int*   idx_s    = reinterpret_cast<int*>(smem + SM_IDX);
    int*   flag_s   = reinterpret_cast<int*>(smem + SM_FLAG);

    const size_t xa = __cvta_generic_to_global(x + (size_t)(m_tile * 128) * F_DIM);
    const size_t wa = __cvta_generic_to_global(W + (size_t)(p * Q_DIM) * F_DIM);

    // ---- async tile loader: 128 rows x 32 f32, XOR-swizzled 16B chunks -----
    auto load_stage = [&](int s) {
        const uint32_t sb = su + (uint32_t)((s % NBUF) * STAGE_BYTES);
        const int kk = s * KT;
#pragma unroll
        for (int u = 0; u < 2; u++) {
            const int tcn = u * THREADS + tid;     // 0..1023 chunk id
            const int row = tcn >> 3;
            const int cc  = tcn & 7;
            const uint32_t dst = sb + (uint32_t)(row * 128 + ((cc ^ (row & 7)) << 4));
            const size_t byte_off = ((size_t)row * F_DIM + kk + cc * 4) * 4;
            CP_ASYNC_16(dst, xa + byte_off);                   // A (x)
            CP_ASYNC_16(dst + TILE_BYTES, wa + byte_off);      // B (W)
        }
        CP_ASYNC_COMMIT();
    };

    // Prefetch first two stages immediately (hide DRAM latency behind setup).
    load_stage(0);
    load_stage(1);

    // ---- detect part_idx dtype (int32 vs int64) ----------------------------
    // True int64 data with values in [0,128): every odd little-endian int32
    // word is 0. For int32 data, P(first 128 odd words all zero) = 128^-64.
    if (wid == 0) {
        const int* p32 = reinterpret_cast<const int*>(part_idx);
        int all0 = 1;
#pragma unroll
        for (int j = 0; j < 4; j++)
            all0 &= (p32[2 * (lid + j * 32) + 1] == 0);
        all0 = __all_sync(0xffffffffu, all0);
        if (lid == 0) *flag_s = all0;
    }
    // Stage bias (region disjoint from GEMM tiles).
    for (int i = tid; i < Q_DIM; i += THREADS)
        bias_s[i] = bias[p * Q_DIM + i];
    __syncthreads();

    // Stage gather indices with the detected stride; mask keeps smem in bounds.
    {
        const int is64 = *flag_s;
        if (is64) {
            const long long* p64 = reinterpret_cast<const long long*>(part_idx);
            for (int i = tid; i < C_DIM; i += THREADS)
                idx_s[i] = ((int)p64[(size_t)p * C_DIM + i]) & 127;
        } else {
            const int* p32 = reinterpret_cast<const int*>(part_idx);
            for (int i = tid; i < C_DIM; i += THREADS)
                idx_s[i] = p32[(size_t)p * C_DIM + i] & 127;
        }
    }

    float c[2][4][4];
#pragma unroll
    for (int mi = 0; mi < 2; mi++)
#pragma unroll
        for (int ni = 0; ni < 4; ni++)
#pragma unroll
            for (int j = 0; j < 4; j++) c[mi][ni][j] = 0.f;

    // ---- mainloop: 3-stage cp.async pipeline -------------------------------
#pragma unroll 1
    for (int s = 0; s < NSTAGES; s++) {
        if (s + 2 < NSTAGES) {
            load_stage(s + 2);
            CP_ASYNC_WAIT(2);
        } else if (s + 1 < NSTAGES) {
            CP_ASYNC_WAIT(1);
        } else {
            CP_ASYNC_WAIT(0);
        }
        __syncthreads();

        const float* As = reinterpret_cast<const float*>(smem + (s % NBUF) * STAGE_BYTES);
        const float* Bs = As + 128 * KT;

#pragma unroll
        for (int ks = 0; ks < 4; ks++) {
            uint32_t a[2][4], b[4][2];
#pragma unroll
            for (int mi = 0; mi < 2; mi++) {
                const int r0  = warp_m * 32 + mi * 16 + g;   // r0+8: same &7
                const int sw0 = (((2 * ks)     ^ (r0 & 7)) << 2) + tg;
                const int sw1 = (((2 * ks + 1) ^ (r0 & 7)) << 2) + tg;
                a[mi][0] = f2tf32(As[r0 * KT + sw0]);
                a[mi][1] = f2tf32(As[(r0 + 8) * KT + sw0]);
                a[mi][2] = f2tf32(As[r0 * KT + sw1]);
                a[mi][3] = f2tf32(As[(r0 + 8) * KT + sw1]);
            }
#pragma unroll
            for (int ni = 0; ni < 4; ni++) {
                const int n0  = warp_n * 32 + ni * 8 + g;
                const int sw0 = (((2 * ks)     ^ (n0 & 7)) << 2) + tg;
                const int sw1 = (((2 * ks + 1) ^ (n0 & 7)) << 2) + tg;
                b[ni][0] = f2tf32(Bs[n0 * KT + sw0]);
                b[ni][1] = f2tf32(Bs[n0 * KT + sw1]);
            }
#pragma unroll
            for (int mi = 0; mi < 2; mi++)
#pragma unroll
                for (int ni = 0; ni < 4; ni++)
                    mma_tf32(c[mi][ni], a[mi], b[ni]);
        }
        __syncthreads();   // protect buffer before the next prefetch overwrite
    }

    // ---- epilogue: logits -> smem (bias added) -----------------------------
#pragma unroll
    for (int mi = 0; mi < 2; mi++) {
        const int r0 = warp_m * 32 + mi * 16 + g;
#pragma unroll
        for (int ni = 0; ni < 4; ni++) {
            const int col = warp_n * 32 + ni * 8 + tg * 2;
            logits_s[r0 * LOGIT_STRIDE + col]           = c[mi][ni][0] + bias_s[col];
            logits_s[r0 * LOGIT_STRIDE + col + 1]       = c[mi][ni][1] + bias_s[col + 1];
            logits_s[(r0 + 8) * LOGIT_STRIDE + col]     = c[mi][ni][2] + bias_s[col];
            logits_s[(r0 + 8) * LOGIT_STRIDE + col + 1] = c[mi][ni][3] + bias_s[col + 1];
        }
    }
    __syncthreads();

    // ---- log_softmax: 4 threads per row (32-elem segments), then combine ---
    {
        const int row = tid & 127;
        const int h   = tid >> 7;            // 0..3
        const float* lrow = logits_s + row * LOGIT_STRIDE + h * 32;
        float m = -1e30f;
#pragma unroll 8
        for (int j = 0; j < 32; j++) m = fmaxf(m, lrow[j]);
        pmax_s[tid] = m;
        __syncthreads();
        const float M = fmaxf(fmaxf(pmax_s[row], pmax_s[row + 128]),
                              fmaxf(pmax_s[row + 256], pmax_s[row + 384]));
        float ssum = 0.f;
#pragma unroll 8
        for (int j = 0; j < 32; j++) ssum += __expf(lrow[j] - M);
        psum_s[tid] = ssum;
        __syncthreads();
        if (tid < 128)
            lse_s[tid] = M + __logf(psum_s[tid] + psum_s[tid + 128] +
                                    psum_s[tid + 256] + psum_s[tid + 384]);
        __syncthreads();
    }

    // ---- gather: out[b, p, c] = logits[b, idx[p,c]] - lse[b] (float4) ------
    {
        const int total4 = 128 * (C_DIM / 4);          // 32000 float4 stores
        float* out_base = out + ((size_t)(m_tile * 128) * P_DIM + p) * C_DIM;
        for (int i = tid; i < total4; i += THREADS) {
            const int r  = i / (C_DIM / 4);
            const int c4 = i - r * (C_DIM / 4);
            const float* lrow = logits_s + r * LOGIT_STRIDE;
            const float  lse  = lse_s[r];
            float4 v;
            v.x = lrow[idx_s[c4 * 4 + 0]] - lse;
            v.y = lrow[idx_s[c4 * 4 + 1]] - lse;
            v.z = lrow[idx_s[c4 * 4 + 2]] - lse;
            v.w = lrow[idx_s[c4 * 4 + 3]] - lse;
            *reinterpret_cast<float4*>(out_base + (size_t)r * P_DIM * C_DIM + c4 * 4) = v;
        }
    }
}

// ============================================================================
// Launch — identify inputs by element count (robust to metadata ordering)
// ============================================================================
extern "C" void kernel_launch(void* const* d_in, const int* in_sizes, int n_in,
                              void* d_out, int out_size) {
    const float* x        = nullptr;   // 256*2048      = 524288
    const float* W        = nullptr;   // 64*128*2048   = 16777216
    const float* bias     = nullptr;   // 64*128        = 8192
    const void*  part_idx = nullptr;   // 64*1000       = 64000

    for (int i = 0; i < n_in; i++) {
        switch (in_sizes[i]) {
            case 524288:   x        = (const float*)d_in[i]; break;
            case 16777216: W        = (const float*)d_in[i]; break;
            case 8192:     bias     = (const float*)d_in[i]; break;
            case 64000:    part_idx = d_in[i];               break;
            default: break;
        }
    }
    if (!x)        x        = (const float*)d_in[0];
    if (!W)        W        = (const float*)d_in[1];
    if (!bias)     bias     = (const float*)d_in[2];
    if (!part_idx) part_idx = d_in[3];

    float* out = (float*)d_out;

    cudaFuncSetAttribute(combinatorial_classifier_kernel,
                         cudaFuncAttributeMaxDynamicSharedMemorySize, SM_TOTAL);

    dim3 grid(2, P_DIM);
    combinatorial_classifier_kernel<<<grid, THREADS, SM_TOTAL>>>(x, W, bias, part_idx, out);
}

// round 9
// speedup vs baseline: 1.0869x; 1.0869x over previous
#include <cuda_runtime.h>
#include <cuda.h>
#include <cstdint>

// ============================================================================
// Problem dims (fixed by the dataset)
// ============================================================================
#define B_DIM 256
#define P_DIM 64
#define Q_DIM 128
#define C_DIM 1000
#define F_DIM 2048

// ============================================================================
// Config
// ============================================================================
static constexpr int THREADS     = 512;          // 16 warps: 4 (m) x 4 (n)
static constexpr int KT          = 32;           // k-elems (fp32) per stage -> 128B rows
static constexpr int NSTAGES     = F_DIM / KT;   // 64
static constexpr int NBUF        = 4;            // TMA pipeline depth
static constexpr int NBUF_CP     = 3;            // cp.async fallback depth
static constexpr int TILE_BYTES  = 128 * KT * 4; // 16384 (A or B tile)
static constexpr int STAGE_BYTES = 2 * TILE_BYTES;   // 32768

// smem layout (bytes). Tile buffers [0, 131072) are reused as the logits
// matrix (128 x 129 fp32, padded stride) post-GEMM.
static constexpr int LOGIT_STRIDE = 129;
static constexpr int SM_LOGITS = 0;                        // 66048 bytes used
static constexpr int SM_BIAS   = NBUF * STAGE_BYTES;       // 131072: 128 f32
static constexpr int SM_LSE    = SM_BIAS + 512;            // 128 f32
static constexpr int SM_PMAX   = SM_LSE + 512;             // 512 f32
static constexpr int SM_PSUM   = SM_PMAX + 2048;           // 512 f32
static constexpr int SM_IDX    = SM_PSUM + 2048;           // 1000 i32 (4000 B)
static constexpr int SM_FLAG   = SM_IDX + 4000;            // 1 i32
static constexpr int SM_MBARS  = SM_IDX + 4008;            // 4 x 8B mbarriers
static constexpr int SM_TOTAL  = SM_IDX + 4096;            // 140288

// ============================================================================
// Helpers
// ============================================================================
__device__ __forceinline__ uint32_t smem_to_u32(const void* smem_ptr) {
    uint32_t addr;
    asm("{ .reg .u64 tmp; cvta.to.shared.u64 tmp, %1; cvt.u32.u64 %0, tmp; }"
        : "=r"(addr) : "l"(smem_ptr));
    return addr;
}

__device__ __forceinline__ uint32_t f2tf32(float f) {
    uint32_t u;
    asm("cvt.rna.tf32.f32 %0, %1;" : "=r"(u) : "f"(f));
    return u;
}

__device__ __forceinline__ void mma_tf32(float* c, const uint32_t* a, const uint32_t* b) {
    asm volatile(
        "mma.sync.aligned.m16n8k8.row.col.f32.tf32.tf32.f32 "
        "{%0,%1,%2,%3}, {%4,%5,%6,%7}, {%8,%9}, {%0,%1,%2,%3};"
        : "+f"(c[0]), "+f"(c[1]), "+f"(c[2]), "+f"(c[3])
        : "r"(a[0]), "r"(a[1]), "r"(a[2]), "r"(a[3]), "r"(b[0]), "r"(b[1]));
}

#define CP_ASYNC_16(dst_u32, src_sz) \
    asm volatile("cp.async.cg.shared.global [%0], [%1], 16;" \
                 :: "r"(dst_u32), "l"(src_sz) : "memory")
#define CP_ASYNC_COMMIT() asm volatile("cp.async.commit_group;" ::: "memory")
#define CP_ASYNC_WAIT(n)  asm volatile("cp.async.wait_group %0;" :: "n"(n) : "memory")

#define MBARRIER_INIT(mbar, count) \
    asm volatile("mbarrier.init.shared.b64 [%0], %1;" \
        :: "r"((uint32_t)(mbar)), "r"((uint32_t)(count)) : "memory")

#define MBARRIER_EXPECT_TX(mbar, bytes) \
    asm volatile("mbarrier.arrive.expect_tx.shared.b64 _, [%0], %1;" \
        :: "r"((uint32_t)(mbar)), "r"((uint32_t)(bytes)) : "memory")

#define MBARRIER_WAIT_PARITY(mbar, parity) do { \
    uint32_t _m = (uint32_t)(mbar); \
    uint32_t _p = (uint32_t)(parity); \
    uint32_t _done; \
    asm volatile( \
        "{\n\t.reg .pred p;\n\t" \
        "mbarrier.try_wait.parity.acquire.cta.shared::cta.b64 p, [%1], %2;\n\t" \
        "selp.b32 %0, 1, 0, p;\n\t}" \
        : "=r"(_done) : "r"(_m), "r"(_p) : "memory"); \
    if (!_done) { \
        asm volatile( \
            "{\n\t.reg .pred P1;\n\t" \
            "WAIT_LOOP_%=:\n\t" \
            "mbarrier.try_wait.parity.acquire.cta.shared::cta.b64 P1, [%0], %1, 0x989680;\n\t" \
            "@P1 bra.uni WAIT_DONE_%=;\n\t" \
            "bra.uni WAIT_LOOP_%=;\n\t" \
            "WAIT_DONE_%=:\n\t}" \
            :: "r"(_m), "r"(_p) : "memory"); \
    } \
} while(0)

__device__ __forceinline__ void tma_load_2d(
    uint32_t dst_smem, const CUtensorMap* tmap,
    int32_t cx, int32_t cy, uint32_t mbar)
{
    asm volatile(
        "cp.async.bulk.tensor.2d.shared::cluster.global.tile.mbarrier::complete_tx::bytes "
        "[%0], [%1, {%2, %3}], [%4];"
        :: "r"(dst_smem), "l"(tmap), "r"(cx), "r"(cy), "r"(mbar)
        : "memory");
}

// ============================================================================
// Shared device subroutines (identical math in both kernel variants)
// ============================================================================
struct WarpCoords {
    int warp_m, warp_n, g, tg;
};

// Consume one 32-k stage from smem tiles at (As, Bs): 4 ks x (LDS + 8 MMA).
__device__ __forceinline__ void consume_stage(
    const float* As, const float* Bs, const WarpCoords& wc, float c[2][4][4])
{
#pragma unroll
    for (int ks = 0; ks < 4; ks++) {
        uint32_t a[2][4], b[4][2];
#pragma unroll
        for (int mi = 0; mi < 2; mi++) {
            const int r0  = wc.warp_m * 32 + mi * 16 + wc.g;   // r0+8: same &7
            const int sw0 = (((2 * ks)     ^ (r0 & 7)) << 2) + wc.tg;
            const int sw1 = (((2 * ks + 1) ^ (r0 & 7)) << 2) + wc.tg;
            a[mi][0] = f2tf32(As[r0 * KT + sw0]);
            a[mi][1] = f2tf32(As[(r0 + 8) * KT + sw0]);
            a[mi][2] = f2tf32(As[r0 * KT + sw1]);
            a[mi][3] = f2tf32(As[(r0 + 8) * KT + sw1]);
        }
#pragma unroll
        for (int ni = 0; ni < 4; ni++) {
            const int n0  = wc.warp_n * 32 + ni * 8 + wc.g;
            const int sw0 = (((2 * ks)     ^ (n0 & 7)) << 2) + wc.tg;
            const int sw1 = (((2 * ks + 1) ^ (n0 & 7)) << 2) + wc.tg;
            b[ni][0] = f2tf32(Bs[n0 * KT + sw0]);
            b[ni][1] = f2tf32(Bs[n0 * KT + sw1]);
        }
#pragma unroll
        for (int mi = 0; mi < 2; mi++)
#pragma unroll
            for (int ni = 0; ni < 4; ni++)
                mma_tf32(c[mi][ni], a[mi], b[ni]);
    }
}

// dtype-detect + stage bias/idx into smem. Call pattern:
//   part A (before a __syncthreads), part B (after it).
__device__ __forceinline__ void stage_meta_a(
    const void* part_idx, const float* bias, int p,
    float* bias_s, int* flag_s, int tid, int wid, int lid)
{
    // int64 data with values in [0,128): every odd little-endian word is 0.
    if (wid == 0) {
        const int* p32 = reinterpret_cast<const int*>(part_idx);
        int all0 = 1;
#pragma unroll
        for (int j = 0; j < 4; j++)
            all0 &= (p32[2 * (lid + j * 32) + 1] == 0);
        all0 = __all_sync(0xffffffffu, all0);
        if (lid == 0) *flag_s = all0;
    }
    for (int i = tid; i < Q_DIM; i += THREADS)
        bias_s[i] = bias[p * Q_DIM + i];
}

__device__ __forceinline__ void stage_meta_b(
    const void* part_idx, int p, int* idx_s, const int* flag_s, int tid)
{
    const int is64 = *flag_s;
    if (is64) {
        const long long* p64 = reinterpret_cast<const long long*>(part_idx);
        for (int i = tid; i < C_DIM; i += THREADS)
            idx_s[i] = ((int)p64[(size_t)p * C_DIM + i]) & 127;
    } else {
        const int* p32 = reinterpret_cast<const int*>(part_idx);
        for (int i = tid; i < C_DIM; i += THREADS)
            idx_s[i] = p32[(size_t)p * C_DIM + i] & 127;
    }
}

// Epilogue: accum -> logits smem (+bias), log_softmax, float4 gather to out.
__device__ __forceinline__ void epilogue(
    float c[2][4][4], const WarpCoords& wc,
    float* logits_s, const float* bias_s, float* lse_s,
    float* pmax_s, float* psum_s, const int* idx_s,
    float* out, int m_tile, int p, int tid)
{
#pragma unroll
    for (int mi = 0; mi < 2; mi++) {
        const int r0 = wc.warp_m * 32 + mi * 16 + wc.g;
#pragma unroll
        for (int ni = 0; ni < 4; ni++) {
            const int col = wc.warp_n * 32 + ni * 8 + wc.tg * 2;
            logits_s[r0 * LOGIT_STRIDE + col]           = c[mi][ni][0] + bias_s[col];
            logits_s[r0 * LOGIT_STRIDE + col + 1]       = c[mi][ni][1] + bias_s[col + 1];
            logits_s[(r0 + 8) * LOGIT_STRIDE + col]     = c[mi][ni][2] + bias_s[col];
            logits_s[(r0 + 8) * LOGIT_STRIDE + col + 1] = c[mi][ni][3] + bias_s[col + 1];
        }
    }
    __syncthreads();

    {   // log_softmax: 4 threads per row (32-elem segments)
        const int row = tid & 127;
        const int h   = tid >> 7;            // 0..3
        const float* lrow = logits_s + row * LOGIT_STRIDE + h * 32;
        float m = -1e30f;
#pragma unroll 8
        for (int j = 0; j < 32; j++) m = fmaxf(m, lrow[j]);
        pmax_s[tid] = m;
        __syncthreads();
        const float M = fmaxf(fmaxf(pmax_s[row], pmax_s[row + 128]),
                              fmaxf(pmax_s[row + 256], pmax_s[row + 384]));
        float ssum = 0.f;
#pragma unroll 8
        for (int j = 0; j < 32; j++) ssum += __expf(lrow[j] - M);
        psum_s[tid] = ssum;
        __syncthreads();
        if (tid < 128)
            lse_s[tid] = M + __logf(psum_s[tid] + psum_s[tid + 128] +
                                    psum_s[tid + 256] + psum_s[tid + 384]);
        __syncthreads();
    }

    {   // gather (float4 stores)
        const int total4 = 128 * (C_DIM / 4);
        float* out_base = out + ((size_t)(m_tile * 128) * P_DIM + p) * C_DIM;
        for (int i = tid; i < total4; i += THREADS) {
            const int r  = i / (C_DIM / 4);
            const int c4 = i - r * (C_DIM / 4);
            const float* lrow = logits_s + r * LOGIT_STRIDE;
            const float  lse  = lse_s[r];
            float4 v;
            v.x = lrow[idx_s[c4 * 4 + 0]] - lse;
            v.y = lrow[idx_s[c4 * 4 + 1]] - lse;
            v.z = lrow[idx_s[c4 * 4 + 2]] - lse;
            v.w = lrow[idx_s[c4 * 4 + 3]] - lse;
            *reinterpret_cast<float4*>(out_base + (size_t)r * P_DIM * C_DIM + c4 * 4) = v;
        }
    }
}

// ============================================================================
// TMA kernel: tile loads via cp.async.bulk.tensor (sm_90 base feature)
// ============================================================================
__global__ void __launch_bounds__(THREADS, 1)
cc_kernel_tma(
    const __grid_constant__ CUtensorMap tma_a,   // x: [256, 2048] f32
    const __grid_constant__ CUtensorMap tma_b,   // W: [8192, 2048] f32
    const float* __restrict__ bias,
    const void*  __restrict__ part_idx,
    float* __restrict__ out)
{
    extern __shared__ char smem[];
    const uint32_t su = smem_to_u32(smem);
    const int tid = threadIdx.x;
    const int wid = tid >> 5;
    const int lid = tid & 31;
    const int m_tile = blockIdx.x;
    const int p      = blockIdx.y;
    WarpCoords wc { wid >> 2, wid & 3, lid >> 2, lid & 3 };

    float* logits_s = reinterpret_cast<float*>(smem + SM_LOGITS);
    float* bias_s   = reinterpret_cast<float*>(smem + SM_BIAS);
    float* lse_s    = reinterpret_cast<float*>(smem + SM_LSE);
    float* pmax_s   = reinterpret_cast<float*>(smem + SM_PMAX);
    float* psum_s   = reinterpret_cast<float*>(smem + SM_PSUM);
    int*   idx_s    = reinterpret_cast<int*>(smem + SM_IDX);
    int*   flag_s   = reinterpret_cast<int*>(smem + SM_FLAG);

    if (tid == 0) {
#pragma unroll
        for (int b = 0; b < NBUF; b++)
            MBARRIER_INIT(su + SM_MBARS + b * 8, 1);
    }
    __syncthreads();

    // Single-thread TMA producer for stage s -> buffer s % NBUF.
    auto issue = [&](int s) {
        const int buf = s & (NBUF - 1);
        const uint32_t sb  = su + (uint32_t)(buf * STAGE_BYTES);
        const uint32_t bar = su + SM_MBARS + buf * 8;
        MBARRIER_EXPECT_TX(bar, STAGE_BYTES);
        tma_load_2d(sb,              &tma_a, s * KT, m_tile * 128, bar);
        tma_load_2d(sb + TILE_BYTES, &tma_b, s * KT, p * 128,      bar);
    };

    if (tid == 0) { issue(0); issue(1); issue(2); }

    stage_meta_a(part_idx, bias, p, bias_s, flag_s, tid, wid, lid);
    __syncthreads();
    stage_meta_b(part_idx, p, idx_s, flag_s, tid);

    float c[2][4][4];
#pragma unroll
    for (int mi = 0; mi < 2; mi++)
#pragma unroll
        for (int ni = 0; ni < 4; ni++)
#pragma unroll
            for (int j = 0; j < 4; j++) c[mi][ni][j] = 0.f;

#pragma unroll 1
    for (int s = 0; s < NSTAGES; s++) {
        // Prefetch distance 3: buffer (s+3)%4 was consumed at stage s-1,
        // whose consumption ended at the __syncthreads below.
        if (tid == 0 && s + 3 < NSTAGES) issue(s + 3);

        const int buf = s & (NBUF - 1);
        MBARRIER_WAIT_PARITY(su + SM_MBARS + buf * 8, (s / NBUF) & 1);

        const float* As = reinterpret_cast<const float*>(smem + buf * STAGE_BYTES);
        const float* Bs = As + 128 * KT;
        consume_stage(As, Bs, wc, c);

        __syncthreads();   // all consumed before tid0 refills this buffer
    }

    epilogue(c, wc, logits_s, bias_s, lse_s, pmax_s, psum_s, idx_s,
             out, m_tile, p, tid);
}

// ============================================================================
// Fallback kernel: proven cp.async path (R8, 94.5us)
// ============================================================================
__global__ void __launch_bounds__(THREADS, 1)
cc_kernel_cp(
    const float* __restrict__ x,
    const float* __restrict__ W,
    const float* __restrict__ bias,
    const void*  __restrict__ part_idx,
    float* __restrict__ out)
{
    extern __shared__ char smem[];
    const uint32_t su = smem_to_u32(smem);
    const int tid = threadIdx.x;
    const int wid = tid >> 5;
    const int lid = tid & 31;
    const int m_tile = blockIdx.x;
    const int p      = blockIdx.y;
    WarpCoords wc { wid >> 2, wid & 3, lid >> 2, lid & 3 };

    float* logits_s = reinterpret_cast<float*>(smem + SM_LOGITS);
    float* bias_s   = reinterpret_cast<float*>(smem + SM_BIAS);
    float* lse_s    = reinterpret_cast<float*>(smem + SM_LSE);
    float* pmax_s   = reinterpret_cast<float*>(smem + SM_PMAX);
    float* psum_s   = reinterpret_cast<float*>(smem + SM_PSUM);
    int*   idx_s    = reinterpret_cast<int*>(smem + SM_IDX);
    int*   flag_s   = reinterpret_cast<int*>(smem + SM_FLAG);

    const size_t xa = __cvta_generic_to_global(x + (size_t)(m_tile * 128) * F_DIM);
    const size_t wa = __cvta_generic_to_global(W + (size_t)(p * Q_DIM) * F_DIM);

    auto load_stage = [&](int s) {
        const uint32_t sb = su + (uint32_t)((s % NBUF_CP) * STAGE_BYTES);
        const int kk = s * KT;
#pragma unroll
        for (int u = 0; u < 2; u++) {
            const int tcn = u * THREADS + tid;
            const int row = tcn >> 3;
            const int cc  = tcn & 7;
            const uint32_t dst = sb + (uint32_t)(row * 128 + ((cc ^ (row & 7)) << 4));
            const size_t byte_off = ((size_t)row * F_DIM + kk + cc * 4) * 4;
            CP_ASYNC_16(dst, xa + byte_off);
            CP_ASYNC_16(dst + TILE_BYTES, wa + byte_off);
        }
        CP_ASYNC_COMMIT();
    };

    load_stage(0);
    load_stage(1);

    stage_meta_a(part_idx, bias, p, bias_s, flag_s, tid, wid, lid);
    __syncthreads();
    stage_meta_b(part_idx, p, idx_s, flag_s, tid);

    float c[2][4][4];
#pragma unroll
    for (int mi = 0; mi < 2; mi++)
#pragma unroll
        for (int ni = 0; ni < 4; ni++)
#pragma unroll
            for (int j = 0; j < 4; j++) c[mi][ni][j] = 0.f;

#pragma unroll 1
    for (int s = 0; s < NSTAGES; s++) {
        if (s + 2 < NSTAGES) {
            load_stage(s + 2);
            CP_ASYNC_WAIT(2);
        } else if (s + 1 < NSTAGES) {
            CP_ASYNC_WAIT(1);
        } else {
            CP_ASYNC_WAIT(0);
        }
        __syncthreads();

        const float* As = reinterpret_cast<const float*>(smem + (s % NBUF_CP) * STAGE_BYTES);
        const float* Bs = As + 128 * KT;
        consume_stage(As, Bs, wc, c);

        __syncthreads();
    }

    epilogue(c, wc, logits_s, bias_s, lse_s, pmax_s, psum_s, idx_s,
             out, m_tile, p, tid);
}

// ============================================================================
// Host: build tensormaps via driver entry point (no -lcuda link dependency)
// ============================================================================
typedef CUresult (*EncodeTiledFn)(
    CUtensorMap*, CUtensorMapDataType, cuuint32_t, void*,
    const cuuint64_t*, const cuuint64_t*, const cuuint32_t*, const cuuint32_t*,
    CUtensorMapInterleave, CUtensorMapSwizzle, CUtensorMapL2promotion,
    CUtensorMapFloatOOBfill);

static bool make_tensormaps(const float* x, const float* W,
                            CUtensorMap* ta, CUtensorMap* tb) {
    EncodeTiledFn fn = nullptr;
    cudaDriverEntryPointQueryResult qr;
#if CUDART_VERSION >= 12050
    if (cudaGetDriverEntryPointByVersion("cuTensorMapEncodeTiled",
            (void**)&fn, 12000, cudaEnableDefault, &qr) != cudaSuccess || !fn)
        return false;
#else
    if (cudaGetDriverEntryPoint("cuTensorMapEncodeTiled",
            (void**)&fn, cudaEnableDefault, &qr) != cudaSuccess || !fn)
        return false;
#endif
    cuuint32_t box[2]  = {(cuuint32_t)KT, 128};   // 32 f32 = 128B inner (SW128 atom)
    cuuint32_t es[2]   = {1, 1};
    {
        cuuint64_t dims[2] = {F_DIM, B_DIM};
        cuuint64_t str[1]  = {F_DIM * 4};
        if (fn(ta, CU_TENSOR_MAP_DATA_TYPE_FLOAT32, 2, (void*)x,
               dims, str, box, es,
               CU_TENSOR_MAP_INTERLEAVE_NONE, CU_TENSOR_MAP_SWIZZLE_128B,
               CU_TENSOR_MAP_L2_PROMOTION_L2_128B,
               CU_TENSOR_MAP_FLOAT_OOB_FILL_NONE) != CUDA_SUCCESS)
            return false;
    }
    {
        cuuint64_t dims[2] = {F_DIM, (cuuint64_t)P_DIM * Q_DIM};
        cuuint64_t str[1]  = {F_DIM * 4};
        if (fn(tb, CU_TENSOR_MAP_DATA_TYPE_FLOAT32, 2, (void*)W,
               dims, str, box, es,
               CU_TENSOR_MAP_INTERLEAVE_NONE, CU_TENSOR_MAP_SWIZZLE_128B,
               CU_TENSOR_MAP_L2_PROMOTION_L2_128B,
               CU_TENSOR_MAP_FLOAT_OOB_FILL_NONE) != CUDA_SUCCESS)
            return false;
    }
    return true;
}

// ============================================================================
// Launch — identify inputs by element count (robust to metadata ordering)
// ============================================================================
extern "C" void kernel_launch(void* const* d_in, const int* in_sizes, int n_in,
                              void* d_out, int out_size) {
    const float* x        = nullptr;   // 256*2048      = 524288
    const float* W        = nullptr;   // 64*128*2048   = 16777216
    const float* bias     = nullptr;   // 64*128        = 8192
    const void*  part_idx = nullptr;   // 64*1000       = 64000

    for (int i = 0; i < n_in; i++) {
        switch (in_sizes[i]) {
            case 524288:   x        = (const float*)d_in[i]; break;
            case 16777216: W        = (const float*)d_in[i]; break;
            case 8192:     bias     = (const float*)d_in[i]; break;
            case 64000:    part_idx = d_in[i];               break;
            default: break;
        }
    }
    if (!x)        x        = (const float*)d_in[0];
    if (!W)        W        = (const float*)d_in[1];
    if (!bias)     bias     = (const float*)d_in[2];
    if (!part_idx) part_idx = d_in[3];

    float* out = (float*)d_out;

    cudaFuncSetAttribute(cc_kernel_tma,
                         cudaFuncAttributeMaxDynamicSharedMemorySize, SM_TOTAL);
    cudaFuncSetAttribute(cc_kernel_cp,
                         cudaFuncAttributeMaxDynamicSharedMemorySize, SM_TOTAL);

    dim3 grid(2, P_DIM);
    CUtensorMap ta, tb;
    if (make_tensormaps(x, W, &ta, &tb)) {
        cc_kernel_tma<<<grid, THREADS, SM_TOTAL>>>(ta, tb, bias, part_idx, out);
    } else {
        cc_kernel_cp<<<grid, THREADS, SM_TOTAL>>>(x, W, bias, part_idx, out);
    }
}

// round 10
// speedup vs baseline: 1.2147x; 1.1176x over previous
#include <cuda_runtime.h>
#include <cuda.h>
#include <cstdint>

// ============================================================================
// Problem dims (fixed by the dataset)
// ============================================================================
#define B_DIM 256
#define P_DIM 64
#define Q_DIM 128
#define C_DIM 1000
#define F_DIM 2048

// ============================================================================
// Config
// ============================================================================
static constexpr int THREADS     = 512;          // 16 warps: 4 (m) x 4 (n)
static constexpr int KT          = 32;           // k-elems (fp32) per stage -> 128B rows
static constexpr int NSTAGES     = F_DIM / KT;   // 64
static constexpr int NBUF        = 4;            // TMA pipeline depth
static constexpr int NBUF_CP     = 3;            // cp.async fallback depth
static constexpr int TILE_BYTES  = 128 * KT * 4; // 16384 (A or B tile)
static constexpr int STAGE_BYTES = 2 * TILE_BYTES;   // 32768

// smem layout (bytes). Tile buffers [0, 131072) are reused as the logits
// matrix (128 x 129 fp32, padded stride) post-GEMM.
static constexpr int LOGIT_STRIDE = 129;
static constexpr int SM_LOGITS = 0;                        // 66048 bytes used
static constexpr int SM_BIAS   = NBUF * STAGE_BYTES;       // 131072: 128 f32
static constexpr int SM_LSE    = SM_BIAS + 512;            // 128 f32
static constexpr int SM_PMAX   = SM_LSE + 512;             // 512 f32
static constexpr int SM_PSUM   = SM_PMAX + 2048;           // 512 f32
static constexpr int SM_IDX    = SM_PSUM + 2048;           // 1000 i32 (4000 B)
static constexpr int SM_FLAG   = SM_IDX + 4000;            // 1 i32
static constexpr int SM_MBARS  = SM_IDX + 4008;            // 4 x 8B mbarriers
static constexpr int SM_TOTAL  = SM_IDX + 4096;            // 140288

// ============================================================================
// Helpers
// ============================================================================
__device__ __forceinline__ uint32_t smem_to_u32(const void* smem_ptr) {
    uint32_t addr;
    asm("{ .reg .u64 tmp; cvta.to.shared.u64 tmp, %1; cvt.u32.u64 %0, tmp; }"
        : "=r"(addr) : "l"(smem_ptr));
    return addr;
}

__device__ __forceinline__ void mma_tf32(float* c, const uint32_t* a, const uint32_t* b) {
    asm volatile(
        "mma.sync.aligned.m16n8k8.row.col.f32.tf32.tf32.f32 "
        "{%0,%1,%2,%3}, {%4,%5,%6,%7}, {%8,%9}, {%0,%1,%2,%3};"
        : "+f"(c[0]), "+f"(c[1]), "+f"(c[2]), "+f"(c[3])
        : "r"(a[0]), "r"(a[1]), "r"(a[2]), "r"(a[3]), "r"(b[0]), "r"(b[1]));
}

#define CP_ASYNC_16(dst_u32, src_sz) \
    asm volatile("cp.async.cg.shared.global [%0], [%1], 16;" \
                 :: "r"(dst_u32), "l"(src_sz) : "memory")
#define CP_ASYNC_COMMIT() asm volatile("cp.async.commit_group;" ::: "memory")
#define CP_ASYNC_WAIT(n)  asm volatile("cp.async.wait_group %0;" :: "n"(n) : "memory")

#define MBARRIER_INIT(mbar, count) \
    asm volatile("mbarrier.init.shared.b64 [%0], %1;" \
        :: "r"((uint32_t)(mbar)), "r"((uint32_t)(count)) : "memory")

#define MBARRIER_EXPECT_TX(mbar, bytes) \
    asm volatile("mbarrier.arrive.expect_tx.shared.b64 _, [%0], %1;" \
        :: "r"((uint32_t)(mbar)), "r"((uint32_t)(bytes)) : "memory")

#define MBARRIER_WAIT_PARITY(mbar, parity) do { \
    uint32_t _m = (uint32_t)(mbar); \
    uint32_t _p = (uint32_t)(parity); \
    uint32_t _done; \
    asm volatile( \
        "{\n\t.reg .pred p;\n\t" \
        "mbarrier.try_wait.parity.acquire.cta.shared::cta.b64 p, [%1], %2;\n\t" \
        "selp.b32 %0, 1, 0, p;\n\t}" \
        : "=r"(_done) : "r"(_m), "r"(_p) : "memory"); \
    if (!_done) { \
        asm volatile( \
            "{\n\t.reg .pred P1;\n\t" \
            "WAIT_LOOP_%=:\n\t" \
            "mbarrier.try_wait.parity.acquire.cta.shared::cta.b64 P1, [%0], %1, 0x989680;\n\t" \
            "@P1 bra.uni WAIT_DONE_%=;\n\t" \
            "bra.uni WAIT_LOOP_%=;\n\t" \
            "WAIT_DONE_%=:\n\t}" \
            :: "r"(_m), "r"(_p) : "memory"); \
    } \
} while(0)

__device__ __forceinline__ void tma_load_2d(
    uint32_t dst_smem, const CUtensorMap* tmap,
    int32_t cx, int32_t cy, uint32_t mbar)
{
    asm volatile(
        "cp.async.bulk.tensor.2d.shared::cluster.global.tile.mbarrier::complete_tx::bytes "
        "[%0], [%1, {%2, %3}], [%4];"
        :: "r"(dst_smem), "l"(tmap), "r"(cx), "r"(cy), "r"(mbar)
        : "memory");
}

// ============================================================================
// Shared device subroutines
// ============================================================================
struct WarpCoords {
    int warp_m, warp_n, g, tg;
};

// Consume one 32-k stage. No cvt (HMMA.TF32 truncates fp32 to tf32 bits);
// addresses folded: r0&7 == g, ((2ks)^g)<<2 == (8ks)^(g<<2), sw1 = sw0^16B.
// Second A row is the +8 row = +1024B immediate from the same pointer.
__device__ __forceinline__ void consume_stage(
    const float* As, const float* Bs, const WarpCoords& wc, float c[2][4][4])
{
    const int g4 = wc.g << 2;        // (g<<2): float-index XOR component
    // Base pointers: row/col base + tg; the per-ks chunk offset is XORed in.
    const uint32_t* aB0 = reinterpret_cast<const uint32_t*>(
        As + (wc.warp_m * 32 + wc.g) * KT + wc.tg);
    const uint32_t* aB1 = aB0 + 16 * KT;  // +16 rows (mi=1)
    const uint32_t* bB0 = reinterpret_cast<const uint32_t*>(
        Bs + (wc.warp_n * 32 + wc.g) * KT + wc.tg);

#pragma unroll
    for (int ks = 0; ks < 4; ks++) {
        const int off  = g4 ^ (8 * ks);      // float offset of chunk sw0
        const int off2 = off ^ 4;            // chunk sw1 (= addr ^ 16B)
        uint32_t a[2][4], b[4][2];
        // A fragments: rows r0, r0+8 (the +8 row = +8*KT floats = +1024B)
        a[0][0] = aB0[off];
        a[0][1] = aB0[off + 8 * KT];
        a[0][2] = aB0[off2];
        a[0][3] = aB0[off2 + 8 * KT];
        a[1][0] = aB1[off];
        a[1][1] = aB1[off + 8 * KT];
        a[1][2] = aB1[off2];
        a[1][3] = aB1[off2 + 8 * KT];
#pragma unroll
        for (int ni = 0; ni < 4; ni++) {
            const uint32_t* bp = bB0 + ni * 8 * KT;
            b[ni][0] = bp[off];
            b[ni][1] = bp[off2];
        }
#pragma unroll
        for (int mi = 0; mi < 2; mi++)
#pragma unroll
            for (int ni = 0; ni < 4; ni++)
                mma_tf32(c[mi][ni], a[mi], b[ni]);
    }
}

__device__ __forceinline__ void stage_meta_a(
    const void* part_idx, const float* bias, int p,
    float* bias_s, int* flag_s, int tid, int wid, int lid)
{
    // int64 data with values in [0,128): every odd little-endian word is 0.
    if (wid == 0) {
        const int* p32 = reinterpret_cast<const int*>(part_idx);
        int all0 = 1;
#pragma unroll
        for (int j = 0; j < 4; j++)
            all0 &= (p32[2 * (lid + j * 32) + 1] == 0);
        all0 = __all_sync(0xffffffffu, all0);
        if (lid == 0) *flag_s = all0;
    }
    for (int i = tid; i < Q_DIM; i += THREADS)
        bias_s[i] = bias[p * Q_DIM + i];
}

__device__ __forceinline__ void stage_meta_b(
    const void* part_idx, int p, int* idx_s, const int* flag_s, int tid)
{
    const int is64 = *flag_s;
    if (is64) {
        const long long* p64 = reinterpret_cast<const long long*>(part_idx);
        for (int i = tid; i < C_DIM; i += THREADS)
            idx_s[i] = ((int)p64[(size_t)p * C_DIM + i]) & 127;
    } else {
        const int* p32 = reinterpret_cast<const int*>(part_idx);
        for (int i = tid; i < C_DIM; i += THREADS)
            idx_s[i] = p32[(size_t)p * C_DIM + i] & 127;
    }
}

__device__ __forceinline__ void epilogue(
    float c[2][4][4], const WarpCoords& wc,
    float* logits_s, const float* bias_s, float* lse_s,
    float* pmax_s, float* psum_s, const int* idx_s,
    float* out, int m_tile, int p, int tid)
{
#pragma unroll
    for (int mi = 0; mi < 2; mi++) {
        const int r0 = wc.warp_m * 32 + mi * 16 + wc.g;
#pragma unroll
        for (int ni = 0; ni < 4; ni++) {
            const int col = wc.warp_n * 32 + ni * 8 + wc.tg * 2;
            logits_s[r0 * LOGIT_STRIDE + col]           = c[mi][ni][0] + bias_s[col];
            logits_s[r0 * LOGIT_STRIDE + col + 1]       = c[mi][ni][1] + bias_s[col + 1];
            logits_s[(r0 + 8) * LOGIT_STRIDE + col]     = c[mi][ni][2] + bias_s[col];
            logits_s[(r0 + 8) * LOGIT_STRIDE + col + 1] = c[mi][ni][3] + bias_s[col + 1];
        }
    }
    __syncthreads();

    {   // log_softmax: 4 threads per row (32-elem segments)
        const int row = tid & 127;
        const int h   = tid >> 7;            // 0..3
        const float* lrow = logits_s + row * LOGIT_STRIDE + h * 32;
        float m = -1e30f;
#pragma unroll 8
        for (int j = 0; j < 32; j++) m = fmaxf(m, lrow[j]);
        pmax_s[tid] = m;
        __syncthreads();
        const float M = fmaxf(fmaxf(pmax_s[row], pmax_s[row + 128]),
                              fmaxf(pmax_s[row + 256], pmax_s[row + 384]));
        float ssum = 0.f;
#pragma unroll 8
        for (int j = 0; j < 32; j++) ssum += __expf(lrow[j] - M);
        psum_s[tid] = ssum;
        __syncthreads();
        if (tid < 128)
            lse_s[tid] = M + __logf(psum_s[tid] + psum_s[tid + 128] +
                                    psum_s[tid + 256] + psum_s[tid + 384]);
        __syncthreads();
    }

    {   // gather (float4 stores)
        const int total4 = 128 * (C_DIM / 4);
        float* out_base = out + ((size_t)(m_tile * 128) * P_DIM + p) * C_DIM;
        for (int i = tid; i < total4; i += THREADS) {
            const int r  = i / (C_DIM / 4);
            const int c4 = i - r * (C_DIM / 4);
            const float* lrow = logits_s + r * LOGIT_STRIDE;
            const float  lse  = lse_s[r];
            float4 v;
            v.x = lrow[idx_s[c4 * 4 + 0]] - lse;
            v.y = lrow[idx_s[c4 * 4 + 1]] - lse;
            v.z = lrow[idx_s[c4 * 4 + 2]] - lse;
            v.w = lrow[idx_s[c4 * 4 + 3]] - lse;
            *reinterpret_cast<float4*>(out_base + (size_t)r * P_DIM * C_DIM + c4 * 4) = v;
        }
    }
}

// ============================================================================
// TMA kernel: 4-buf pipeline, one __syncthreads per stage, refill dist = NBUF
// ============================================================================
__global__ void __launch_bounds__(THREADS, 1)
cc_kernel_tma(
    const __grid_constant__ CUtensorMap tma_a,   // x: [256, 2048] f32
    const __grid_constant__ CUtensorMap tma_b,   // W: [8192, 2048] f32
    const float* __restrict__ bias,
    const void*  __restrict__ part_idx,
    float* __restrict__ out)
{
    extern __shared__ char smem[];
    const uint32_t su = smem_to_u32(smem);
    const int tid = threadIdx.x;
    const int wid = tid >> 5;
    const int lid = tid & 31;
    const int m_tile = blockIdx.x;
    const int p      = blockIdx.y;
    WarpCoords wc { wid >> 2, wid & 3, lid >> 2, lid & 3 };

    float* logits_s = reinterpret_cast<float*>(smem + SM_LOGITS);
    float* bias_s   = reinterpret_cast<float*>(smem + SM_BIAS);
    float* lse_s    = reinterpret_cast<float*>(smem + SM_LSE);
    float* pmax_s   = reinterpret_cast<float*>(smem + SM_PMAX);
    float* psum_s   = reinterpret_cast<float*>(smem + SM_PSUM);
    int*   idx_s    = reinterpret_cast<int*>(smem + SM_IDX);
    int*   flag_s   = reinterpret_cast<int*>(smem + SM_FLAG);

    if (tid == 0) {
#pragma unroll
        for (int b = 0; b < NBUF; b++)
            MBARRIER_INIT(su + SM_MBARS + b * 8, 1);
    }
    __syncthreads();

    auto issue = [&](int s) {
        const int buf = s & (NBUF - 1);
        const uint32_t sb  = su + (uint32_t)(buf * STAGE_BYTES);
        const uint32_t bar = su + SM_MBARS + buf * 8;
        MBARRIER_EXPECT_TX(bar, STAGE_BYTES);
        tma_load_2d(sb,              &tma_a, s * KT, m_tile * 128, bar);
        tma_load_2d(sb + TILE_BYTES, &tma_b, s * KT, p * 128,      bar);
    };

    if (tid == 0) { issue(0); issue(1); issue(2); issue(3); }

    stage_meta_a(part_idx, bias, p, bias_s, flag_s, tid, wid, lid);
    __syncthreads();
    stage_meta_b(part_idx, p, idx_s, flag_s, tid);

    float c[2][4][4];
#pragma unroll
    for (int mi = 0; mi < 2; mi++)
#pragma unroll
        for (int ni = 0; ni < 4; ni++)
#pragma unroll
            for (int j = 0; j < 4; j++) c[mi][ni][j] = 0.f;

#pragma unroll 1
    for (int s = 0; s < NSTAGES; s++) {
        const int buf = s & (NBUF - 1);
        MBARRIER_WAIT_PARITY(su + SM_MBARS + buf * 8, (s >> 2) & 1);

        const float* As = reinterpret_cast<const float*>(smem + buf * STAGE_BYTES);
        const float* Bs = As + 128 * KT;
        consume_stage(As, Bs, wc, c);

        __syncthreads();   // everyone consumed buf s before tid0 refills it
        if (tid == 0 && s + NBUF < NSTAGES) issue(s + NBUF);
    }

    epilogue(c, wc, logits_s, bias_s, lse_s, pmax_s, psum_s, idx_s,
             out, m_tile, p, tid);
}

// ============================================================================
// Fallback kernel: cp.async path (same consume/epilogue)
// ============================================================================
__global__ void __launch_bounds__(THREADS, 1)
cc_kernel_cp(
    const float* __restrict__ x,
    const float* __restrict__ W,
    const float* __restrict__ bias,
    const void*  __restrict__ part_idx,
    float* __restrict__ out)
{
    extern __shared__ char smem[];
    const uint32_t su = smem_to_u32(smem);
    const int tid = threadIdx.x;
    const int wid = tid >> 5;
    const int lid = tid & 31;
    const int m_tile = blockIdx.x;
    const int p      = blockIdx.y;
    WarpCoords wc { wid >> 2, wid & 3, lid >> 2, lid & 3 };

    float* logits_s = reinterpret_cast<float*>(smem + SM_LOGITS);
    float* bias_s   = reinterpret_cast<float*>(smem + SM_BIAS);
    float* lse_s    = reinterpret_cast<float*>(smem + SM_LSE);
    float* pmax_s   = reinterpret_cast<float*>(smem + SM_PMAX);
    float* psum_s   = reinterpret_cast<float*>(smem + SM_PSUM);
    int*   idx_s    = reinterpret_cast<int*>(smem + SM_IDX);
    int*   flag_s   = reinterpret_cast<int*>(smem + SM_FLAG);

    const size_t xa = __cvta_generic_to_global(x + (size_t)(m_tile * 128) * F_DIM);
    const size_t wa = __cvta_generic_to_global(W + (size_t)(p * Q_DIM) * F_DIM);

    auto load_stage = [&](int s) {
        const uint32_t sb = su + (uint32_t)((s % NBUF_CP) * STAGE_BYTES);
        const int kk = s * KT;
#pragma unroll
        for (int u = 0; u < 2; u++) {
            const int tcn = u * THREADS + tid;
            const int row = tcn >> 3;
            const int cc  = tcn & 7;
            const uint32_t dst = sb + (uint32_t)(row * 128 + ((cc ^ (row & 7)) << 4));
            const size_t byte_off = ((size_t)row * F_DIM + kk + cc * 4) * 4;
            CP_ASYNC_16(dst, xa + byte_off);
            CP_ASYNC_16(dst + TILE_BYTES, wa + byte_off);
        }
        CP_ASYNC_COMMIT();
    };

    load_stage(0);
    load_stage(1);

    stage_meta_a(part_idx, bias, p, bias_s, flag_s, tid, wid, lid);
    __syncthreads();
    stage_meta_b(part_idx, p, idx_s, flag_s, tid);

    float c[2][4][4];
#pragma unroll
    for (int mi = 0; mi < 2; mi++)
#pragma unroll
        for (int ni = 0; ni < 4; ni++)
#pragma unroll
            for (int j = 0; j < 4; j++) c[mi][ni][j] = 0.f;

#pragma unroll 1
    for (int s = 0; s < NSTAGES; s++) {
        if (s + 2 < NSTAGES) {
            load_stage(s + 2);
            CP_ASYNC_WAIT(2);
        } else if (s + 1 < NSTAGES) {
            CP_ASYNC_WAIT(1);
        } else {
            CP_ASYNC_WAIT(0);
        }
        __syncthreads();

        const float* As = reinterpret_cast<const float*>(smem + (s % NBUF_CP) * STAGE_BYTES);
        const float* Bs = As + 128 * KT;
        consume_stage(As, Bs, wc, c);

        __syncthreads();
    }

    epilogue(c, wc, logits_s, bias_s, lse_s, pmax_s, psum_s, idx_s,
             out, m_tile, p, tid);
}

// ============================================================================
// Host: build tensormaps via driver entry point (no -lcuda link dependency)
// ============================================================================
typedef CUresult (*EncodeTiledFn)(
    CUtensorMap*, CUtensorMapDataType, cuuint32_t, void*,
    const cuuint64_t*, const cuuint64_t*, const cuuint32_t*, const cuuint32_t*,
    CUtensorMapInterleave, CUtensorMapSwizzle, CUtensorMapL2promotion,
    CUtensorMapFloatOOBfill);

static bool make_tensormaps(const float* x, const float* W,
                            CUtensorMap* ta, CUtensorMap* tb) {
    EncodeTiledFn fn = nullptr;
    cudaDriverEntryPointQueryResult qr;
#if CUDART_VERSION >= 12050
    if (cudaGetDriverEntryPointByVersion("cuTensorMapEncodeTiled",
            (void**)&fn, 12000, cudaEnableDefault, &qr) != cudaSuccess || !fn)
        return false;
#else
    if (cudaGetDriverEntryPoint("cuTensorMapEncodeTiled",
            (void**)&fn, cudaEnableDefault, &qr) != cudaSuccess || !fn)
        return false;
#endif
    cuuint32_t box[2]  = {(cuuint32_t)KT, 128};   // 32 f32 = 128B inner (SW128 atom)
    cuuint32_t es[2]   = {1, 1};
    {
        cuuint64_t dims[2] = {F_DIM, B_DIM};
        cuuint64_t str[1]  = {F_DIM * 4};
        if (fn(ta, CU_TENSOR_MAP_DATA_TYPE_FLOAT32, 2, (void*)x,
               dims, str, box, es,
               CU_TENSOR_MAP_INTERLEAVE_NONE, CU_TENSOR_MAP_SWIZZLE_128B,
               CU_TENSOR_MAP_L2_PROMOTION_L2_128B,
               CU_TENSOR_MAP_FLOAT_OOB_FILL_NONE) != CUDA_SUCCESS)
            return false;
    }
    {
        cuuint64_t dims[2] = {F_DIM, (cuuint64_t)P_DIM * Q_DIM};
        cuuint64_t str[1]  = {F_DIM * 4};
        if (fn(tb, CU_TENSOR_MAP_DATA_TYPE_FLOAT32, 2, (void*)W,
               dims, str, box, es,
               CU_TENSOR_MAP_INTERLEAVE_NONE, CU_TENSOR_MAP_SWIZZLE_128B,
               CU_TENSOR_MAP_L2_PROMOTION_L2_128B,
               CU_TENSOR_MAP_FLOAT_OOB_FILL_NONE) != CUDA_SUCCESS)
            return false;
    }
    return true;
}

// ============================================================================
// Launch — identify inputs by element count (robust to metadata ordering)
// ============================================================================
extern "C" void kernel_launch(void* const* d_in, const int* in_sizes, int n_in,
                              void* d_out, int out_size) {
    const float* x        = nullptr;   // 256*2048      = 524288
    const float* W        = nullptr;   // 64*128*2048   = 16777216
    const float* bias     = nullptr;   // 64*128        = 8192
    const void*  part_idx = nullptr;   // 64*1000       = 64000

    for (int i = 0; i < n_in; i++) {
        switch (in_sizes[i]) {
            case 524288:   x        = (const float*)d_in[i]; break;
            case 16777216: W        = (const float*)d_in[i]; break;
            case 8192:     bias     = (const float*)d_in[i]; break;
            case 64000:    part_idx = d_in[i];               break;
            default: break;
        }
    }
    if (!x)        x        = (const float*)d_in[0];
    if (!W)        W        = (const float*)d_in[1];
    if (!bias)     bias     = (const float*)d_in[2];
    if (!part_idx) part_idx = d_in[3];

    float* out = (float*)d_out;

    cudaFuncSetAttribute(cc_kernel_tma,
                         cudaFuncAttributeMaxDynamicSharedMemorySize, SM_TOTAL);
    cudaFuncSetAttribute(cc_kernel_cp,
                         cudaFuncAttributeMaxDynamicSharedMemorySize, SM_TOTAL);

    dim3 grid(2, P_DIM);
    CUtensorMap ta, tb;
    if (make_tensormaps(x, W, &ta, &tb)) {
        cc_kernel_tma<<<grid, THREADS, SM_TOTAL>>>(ta, tb, bias, part_idx, out);
    } else {
        cc_kernel_cp<<<grid, THREADS, SM_TOTAL>>>(x, W, bias, part_idx, out);
    }
}

// round 11
// speedup vs baseline: 1.2418x; 1.0223x over previous
#include <cuda_runtime.h>
#include <cuda.h>
#include <cstdint>

// ============================================================================
// Problem dims (fixed by the dataset)
// ============================================================================
#define B_DIM 256
#define P_DIM 64
#define Q_DIM 128
#define C_DIM 1000
#define F_DIM 2048

// ============================================================================
// Config: 64-row m-tiles, 2 CTAs/SM for stall overlap
// ============================================================================
static constexpr int THREADS     = 256;          // 8 warps: 2 (m) x 4 (n)
static constexpr int M_TILE      = 64;           // batch rows per CTA
static constexpr int KT          = 32;           // k-elems (fp32) per stage -> 128B rows
static constexpr int NSTAGES     = F_DIM / KT;   // 64
static constexpr int NBUF        = 4;            // TMA pipeline depth
static constexpr int NBUF_CP     = 3;            // cp.async fallback depth
static constexpr int A_TILE_BYTES = M_TILE * KT * 4;  // 8192
static constexpr int B_TILE_BYTES = 128 * KT * 4;     // 16384
static constexpr int STAGE_BYTES  = A_TILE_BYTES + B_TILE_BYTES;  // 24576

// smem layout (bytes). Tile buffers reused as logits (64 x 129 f32) post-GEMM.
static constexpr int LOGIT_STRIDE = 129;
static constexpr int SM_LOGITS = 0;                        // 33024 bytes used
static constexpr int SM_BIAS   = NBUF * STAGE_BYTES;       // 98304: 128 f32
static constexpr int SM_LSE    = SM_BIAS + 512;            // 64 f32
static constexpr int SM_PMAX   = SM_LSE + 512;             // 256 f32
static constexpr int SM_PSUM   = SM_PMAX + 1024;           // 256 f32
static constexpr int SM_IDX    = SM_PSUM + 1024;           // 1000 i32 (4000 B)
static constexpr int SM_FLAG   = SM_IDX + 4000;            // 1 i32
static constexpr int SM_MBARS  = SM_IDX + 4008;            // 4 x 8B mbarriers
static constexpr int SM_TOTAL  = SM_IDX + 4096;            // 105472  (x2 = 211KB/SM)

// ============================================================================
// Helpers
// ============================================================================
__device__ __forceinline__ uint32_t smem_to_u32(const void* smem_ptr) {
    uint32_t addr;
    asm("{ .reg .u64 tmp; cvta.to.shared.u64 tmp, %1; cvt.u32.u64 %0, tmp; }"
        : "=r"(addr) : "l"(smem_ptr));
    return addr;
}

__device__ __forceinline__ void mma_tf32(float* c, const uint32_t* a, const uint32_t* b) {
    asm volatile(
        "mma.sync.aligned.m16n8k8.row.col.f32.tf32.tf32.f32 "
        "{%0,%1,%2,%3}, {%4,%5,%6,%7}, {%8,%9}, {%0,%1,%2,%3};"
        : "+f"(c[0]), "+f"(c[1]), "+f"(c[2]), "+f"(c[3])
        : "r"(a[0]), "r"(a[1]), "r"(a[2]), "r"(a[3]), "r"(b[0]), "r"(b[1]));
}

#define CP_ASYNC_16(dst_u32, src_sz) \
    asm volatile("cp.async.cg.shared.global [%0], [%1], 16;" \
                 :: "r"(dst_u32), "l"(src_sz) : "memory")
#define CP_ASYNC_COMMIT() asm volatile("cp.async.commit_group;" ::: "memory")
#define CP_ASYNC_WAIT(n)  asm volatile("cp.async.wait_group %0;" :: "n"(n) : "memory")

#define MBARRIER_INIT(mbar, count) \
    asm volatile("mbarrier.init.shared.b64 [%0], %1;" \
        :: "r"((uint32_t)(mbar)), "r"((uint32_t)(count)) : "memory")

#define MBARRIER_EXPECT_TX(mbar, bytes) \
    asm volatile("mbarrier.arrive.expect_tx.shared.b64 _, [%0], %1;" \
        :: "r"((uint32_t)(mbar)), "r"((uint32_t)(bytes)) : "memory")

#define MBARRIER_WAIT_PARITY(mbar, parity) do { \
    uint32_t _m = (uint32_t)(mbar); \
    uint32_t _p = (uint32_t)(parity); \
    uint32_t _done; \
    asm volatile( \
        "{\n\t.reg .pred p;\n\t" \
        "mbarrier.try_wait.parity.acquire.cta.shared::cta.b64 p, [%1], %2;\n\t" \
        "selp.b32 %0, 1, 0, p;\n\t}" \
        : "=r"(_done) : "r"(_m), "r"(_p) : "memory"); \
    if (!_done) { \
        asm volatile( \
            "{\n\t.reg .pred P1;\n\t" \
            "WAIT_LOOP_%=:\n\t" \
            "mbarrier.try_wait.parity.acquire.cta.shared::cta.b64 P1, [%0], %1, 0x989680;\n\t" \
            "@P1 bra.uni WAIT_DONE_%=;\n\t" \
            "bra.uni WAIT_LOOP_%=;\n\t" \
            "WAIT_DONE_%=:\n\t}" \
            :: "r"(_m), "r"(_p) : "memory"); \
    } \
} while(0)

__device__ __forceinline__ void tma_load_2d(
    uint32_t dst_smem, const CUtensorMap* tmap,
    int32_t cx, int32_t cy, uint32_t mbar)
{
    asm volatile(
        "cp.async.bulk.tensor.2d.shared::cluster.global.tile.mbarrier::complete_tx::bytes "
        "[%0], [%1, {%2, %3}], [%4];"
        :: "r"(dst_smem), "l"(tmap), "r"(cx), "r"(cy), "r"(mbar)
        : "memory");
}

// ============================================================================
// Shared device subroutines
// ============================================================================
struct WarpCoords {
    int warp_m, warp_n, g, tg;
};

// Consume one 32-k stage. No cvt (HMMA.TF32 truncates fp32 bits); addresses
// folded: r0&7==g, ((2ks)^g)<<2 == (8ks)^(g<<2), sw1 = sw0^16B.
__device__ __forceinline__ void consume_stage(
    const float* As, const float* Bs, const WarpCoords& wc, float c[2][4][4])
{
    const int g4 = wc.g << 2;
    const uint32_t* aB0 = reinterpret_cast<const uint32_t*>(
        As + (wc.warp_m * 32 + wc.g) * KT + wc.tg);
    const uint32_t* aB1 = aB0 + 16 * KT;
    const uint32_t* bB0 = reinterpret_cast<const uint32_t*>(
        Bs + (wc.warp_n * 32 + wc.g) * KT + wc.tg);

#pragma unroll
    for (int ks = 0; ks < 4; ks++) {
        const int off  = g4 ^ (8 * ks);
        const int off2 = off ^ 4;
        uint32_t a[2][4], b[4][2];
        a[0][0] = aB0[off];
        a[0][1] = aB0[off + 8 * KT];
        a[0][2] = aB0[off2];
        a[0][3] = aB0[off2 + 8 * KT];
        a[1][0] = aB1[off];
        a[1][1] = aB1[off + 8 * KT];
        a[1][2] = aB1[off2];
        a[1][3] = aB1[off2 + 8 * KT];
#pragma unroll
        for (int ni = 0; ni < 4; ni++) {
            const uint32_t* bp = bB0 + ni * 8 * KT;
            b[ni][0] = bp[off];
            b[ni][1] = bp[off2];
        }
#pragma unroll
        for (int mi = 0; mi < 2; mi++)
#pragma unroll
            for (int ni = 0; ni < 4; ni++)
                mma_tf32(c[mi][ni], a[mi], b[ni]);
    }
}

__device__ __forceinline__ void stage_meta_a(
    const void* part_idx, const float* bias, int p,
    float* bias_s, int* flag_s, int tid, int wid, int lid)
{
    // int64 data with values in [0,128): every odd little-endian word is 0.
    if (wid == 0) {
        const int* p32 = reinterpret_cast<const int*>(part_idx);
        int all0 = 1;
#pragma unroll
        for (int j = 0; j < 4; j++)
            all0 &= (p32[2 * (lid + j * 32) + 1] == 0);
        all0 = __all_sync(0xffffffffu, all0);
        if (lid == 0) *flag_s = all0;
    }
    for (int i = tid; i < Q_DIM; i += THREADS)
        bias_s[i] = bias[p * Q_DIM + i];
}

__device__ __forceinline__ void stage_meta_b(
    const void* part_idx, int p, int* idx_s, const int* flag_s, int tid)
{
    const int is64 = *flag_s;
    if (is64) {
        const long long* p64 = reinterpret_cast<const long long*>(part_idx);
        for (int i = tid; i < C_DIM; i += THREADS)
            idx_s[i] = ((int)p64[(size_t)p * C_DIM + i]) & 127;
    } else {
        const int* p32 = reinterpret_cast<const int*>(part_idx);
        for (int i = tid; i < C_DIM; i += THREADS)
            idx_s[i] = p32[(size_t)p * C_DIM + i] & 127;
    }
}

__device__ __forceinline__ void epilogue(
    float c[2][4][4], const WarpCoords& wc,
    float* logits_s, const float* bias_s, float* lse_s,
    float* pmax_s, float* psum_s, const int* idx_s,
    float* out, int m_tile, int p, int tid)
{
#pragma unroll
    for (int mi = 0; mi < 2; mi++) {
        const int r0 = wc.warp_m * 32 + mi * 16 + wc.g;   // 0..63
#pragma unroll
        for (int ni = 0; ni < 4; ni++) {
            const int col = wc.warp_n * 32 + ni * 8 + wc.tg * 2;
            logits_s[r0 * LOGIT_STRIDE + col]           = c[mi][ni][0] + bias_s[col];
            logits_s[r0 * LOGIT_STRIDE + col + 1]       = c[mi][ni][1] + bias_s[col + 1];
            logits_s[(r0 + 8) * LOGIT_STRIDE + col]     = c[mi][ni][2] + bias_s[col];
            logits_s[(r0 + 8) * LOGIT_STRIDE + col + 1] = c[mi][ni][3] + bias_s[col + 1];
        }
    }
    __syncthreads();

    {   // log_softmax: 4 threads per row (32-elem segments), 64 rows
        const int row = tid & 63;
        const int h   = tid >> 6;            // 0..3
        const float* lrow = logits_s + row * LOGIT_STRIDE + h * 32;
        float m = -1e30f;
#pragma unroll 8
        for (int j = 0; j < 32; j++) m = fmaxf(m, lrow[j]);
        pmax_s[tid] = m;
        __syncthreads();
        const float M = fmaxf(fmaxf(pmax_s[row], pmax_s[row + 64]),
                              fmaxf(pmax_s[row + 128], pmax_s[row + 192]));
        float ssum = 0.f;
#pragma unroll 8
        for (int j = 0; j < 32; j++) ssum += __expf(lrow[j] - M);
        psum_s[tid] = ssum;
        __syncthreads();
        if (tid < 64)
            lse_s[tid] = M + __logf(psum_s[tid] + psum_s[tid + 64] +
                                    psum_s[tid + 128] + psum_s[tid + 192]);
        __syncthreads();
    }

    {   // gather (float4 stores)
        const int total4 = M_TILE * (C_DIM / 4);       // 16000
        float* out_base = out + ((size_t)(m_tile * M_TILE) * P_DIM + p) * C_DIM;
        for (int i = tid; i < total4; i += THREADS) {
            const int r  = i / (C_DIM / 4);
            const int c4 = i - r * (C_DIM / 4);
            const float* lrow = logits_s + r * LOGIT_STRIDE;
            const float  lse  = lse_s[r];
            float4 v;
            v.x = lrow[idx_s[c4 * 4 + 0]] - lse;
            v.y = lrow[idx_s[c4 * 4 + 1]] - lse;
            v.z = lrow[idx_s[c4 * 4 + 2]] - lse;
            v.w = lrow[idx_s[c4 * 4 + 3]] - lse;
            *reinterpret_cast<float4*>(out_base + (size_t)r * P_DIM * C_DIM + c4 * 4) = v;
        }
    }
}

// ============================================================================
// TMA kernel: 4-buf pipeline, one __syncthreads per stage, refill dist = NBUF
// ============================================================================
__global__ void __launch_bounds__(THREADS, 2)
cc_kernel_tma(
    const __grid_constant__ CUtensorMap tma_a,   // x: [256, 2048] f32
    const __grid_constant__ CUtensorMap tma_b,   // W: [8192, 2048] f32
    const float* __restrict__ bias,
    const void*  __restrict__ part_idx,
    float* __restrict__ out)
{
    extern __shared__ char smem[];
    const uint32_t su = smem_to_u32(smem);
    const int tid = threadIdx.x;
    const int wid = tid >> 5;
    const int lid = tid & 31;
    const int m_tile = blockIdx.x;               // 0..3 (64 rows each)
    const int p      = blockIdx.y;               // 0..63
    WarpCoords wc { wid >> 2, wid & 3, lid >> 2, lid & 3 };

    float* logits_s = reinterpret_cast<float*>(smem + SM_LOGITS);
    float* bias_s   = reinterpret_cast<float*>(smem + SM_BIAS);
    float* lse_s    = reinterpret_cast<float*>(smem + SM_LSE);
    float* pmax_s   = reinterpret_cast<float*>(smem + SM_PMAX);
    float* psum_s   = reinterpret_cast<float*>(smem + SM_PSUM);
    int*   idx_s    = reinterpret_cast<int*>(smem + SM_IDX);
    int*   flag_s   = reinterpret_cast<int*>(smem + SM_FLAG);

    if (tid == 0) {
#pragma unroll
        for (int b = 0; b < NBUF; b++)
            MBARRIER_INIT(su + SM_MBARS + b * 8, 1);
    }
    __syncthreads();

    auto issue = [&](int s) {
        const int buf = s & (NBUF - 1);
        const uint32_t sb  = su + (uint32_t)(buf * STAGE_BYTES);
        const uint32_t bar = su + SM_MBARS + buf * 8;
        MBARRIER_EXPECT_TX(bar, STAGE_BYTES);
        tma_load_2d(sb,                &tma_a, s * KT, m_tile * M_TILE, bar);
        tma_load_2d(sb + A_TILE_BYTES, &tma_b, s * KT, p * 128,         bar);
    };

    if (tid == 0) { issue(0); issue(1); issue(2); issue(3); }

    stage_meta_a(part_idx, bias, p, bias_s, flag_s, tid, wid, lid);
    __syncthreads();
    stage_meta_b(part_idx, p, idx_s, flag_s, tid);

    float c[2][4][4];
#pragma unroll
    for (int mi = 0; mi < 2; mi++)
#pragma unroll
        for (int ni = 0; ni < 4; ni++)
#pragma unroll
            for (int j = 0; j < 4; j++) c[mi][ni][j] = 0.f;

#pragma unroll 1
    for (int s = 0; s < NSTAGES; s++) {
        const int buf = s & (NBUF - 1);
        MBARRIER_WAIT_PARITY(su + SM_MBARS + buf * 8, (s >> 2) & 1);

        const float* As = reinterpret_cast<const float*>(smem + buf * STAGE_BYTES);
        const float* Bs = As + M_TILE * KT;
        consume_stage(As, Bs, wc, c);

        __syncthreads();   // everyone consumed buf s before tid0 refills it
        if (tid == 0 && s + NBUF < NSTAGES) issue(s + NBUF);
    }

    epilogue(c, wc, logits_s, bias_s, lse_s, pmax_s, psum_s, idx_s,
             out, m_tile, p, tid);
}

// ============================================================================
// Fallback kernel: cp.async path (same consume/epilogue)
// ============================================================================
__global__ void __launch_bounds__(THREADS, 2)
cc_kernel_cp(
    const float* __restrict__ x,
    const float* __restrict__ W,
    const float* __restrict__ bias,
    const void*  __restrict__ part_idx,
    float* __restrict__ out)
{
    extern __shared__ char smem[];
    const uint32_t su = smem_to_u32(smem);
    const int tid = threadIdx.x;
    const int wid = tid >> 5;
    const int lid = tid & 31;
    const int m_tile = blockIdx.x;
    const int p      = blockIdx.y;
    WarpCoords wc { wid >> 2, wid & 3, lid >> 2, lid & 3 };

    float* logits_s = reinterpret_cast<float*>(smem + SM_LOGITS);
    float* bias_s   = reinterpret_cast<float*>(smem + SM_BIAS);
    float* lse_s    = reinterpret_cast<float*>(smem + SM_LSE);
    float* pmax_s   = reinterpret_cast<float*>(smem + SM_PMAX);
    float* psum_s   = reinterpret_cast<float*>(smem + SM_PSUM);
    int*   idx_s    = reinterpret_cast<int*>(smem + SM_IDX);
    int*   flag_s   = reinterpret_cast<int*>(smem + SM_FLAG);

    const size_t xa = __cvta_generic_to_global(x + (size_t)(m_tile * M_TILE) * F_DIM);
    const size_t wa = __cvta_generic_to_global(W + (size_t)(p * Q_DIM) * F_DIM);

    auto load_stage = [&](int s) {
        const uint32_t sb = su + (uint32_t)((s % NBUF_CP) * STAGE_BYTES);
        const int kk = s * KT;
        // A: 64 rows x 8 chunks = 512
#pragma unroll
        for (int u = 0; u < 2; u++) {
            const int tcn = u * THREADS + tid;
            const int row = tcn >> 3;
            const int cc  = tcn & 7;
            const uint32_t dst = sb + (uint32_t)(row * 128 + ((cc ^ (row & 7)) << 4));
            CP_ASYNC_16(dst, xa + ((size_t)row * F_DIM + kk + cc * 4) * 4);
        }
        // B: 128 rows x 8 chunks = 1024
#pragma unroll
        for (int u = 0; u < 4; u++) {
            const int tcn = u * THREADS + tid;
            const int row = tcn >> 3;
            const int cc  = tcn & 7;
            const uint32_t dst = sb + A_TILE_BYTES
                               + (uint32_t)(row * 128 + ((cc ^ (row & 7)) << 4));
            CP_ASYNC_16(dst, wa + ((size_t)row * F_DIM + kk + cc * 4) * 4);
        }
        CP_ASYNC_COMMIT();
    };

    load_stage(0);
    load_stage(1);

    stage_meta_a(part_idx, bias, p, bias_s, flag_s, tid, wid, lid);
    __syncthreads();
    stage_meta_b(part_idx, p, idx_s, flag_s, tid);

    float c[2][4][4];
#pragma unroll
    for (int mi = 0; mi < 2; mi++)
#pragma unroll
        for (int ni = 0; ni < 4; ni++)
#pragma unroll
            for (int j = 0; j < 4; j++) c[mi][ni][j] = 0.f;

#pragma unroll 1
    for (int s = 0; s < NSTAGES; s++) {
        if (s + 2 < NSTAGES) {
            load_stage(s + 2);
            CP_ASYNC_WAIT(2);
        } else if (s + 1 < NSTAGES) {
            CP_ASYNC_WAIT(1);
        } else {
            CP_ASYNC_WAIT(0);
        }
        __syncthreads();

        const float* As = reinterpret_cast<const float*>(smem + (s % NBUF_CP) * STAGE_BYTES);
        const float* Bs = As + M_TILE * KT;
        consume_stage(As, Bs, wc, c);

        __syncthreads();
    }

    epilogue(c, wc, logits_s, bias_s, lse_s, pmax_s, psum_s, idx_s,
             out, m_tile, p, tid);
}

// ============================================================================
// Host: build tensormaps via driver entry point (no -lcuda link dependency)
// ============================================================================
typedef CUresult (*EncodeTiledFn)(
    CUtensorMap*, CUtensorMapDataType, cuuint32_t, void*,
    const cuuint64_t*, const cuuint64_t*, const cuuint32_t*, const cuuint32_t*,
    CUtensorMapInterleave, CUtensorMapSwizzle, CUtensorMapL2promotion,
    CUtensorMapFloatOOBfill);

static bool make_tensormaps(const float* x, const float* W,
                            CUtensorMap* ta, CUtensorMap* tb) {
    EncodeTiledFn fn = nullptr;
    cudaDriverEntryPointQueryResult qr;
#if CUDART_VERSION >= 12050
    if (cudaGetDriverEntryPointByVersion("cuTensorMapEncodeTiled",
            (void**)&fn, 12000, cudaEnableDefault, &qr) != cudaSuccess || !fn)
        return false;
#else
    if (cudaGetDriverEntryPoint("cuTensorMapEncodeTiled",
            (void**)&fn, cudaEnableDefault, &qr) != cudaSuccess || !fn)
        return false;
#endif
    cuuint32_t es[2] = {1, 1};
    {
        cuuint32_t box[2]  = {(cuuint32_t)KT, (cuuint32_t)M_TILE};
        cuuint64_t dims[2] = {F_DIM, B_DIM};
        cuuint64_t str[1]  = {F_DIM * 4};
        if (fn(ta, CU_TENSOR_MAP_DATA_TYPE_FLOAT32, 2, (void*)x,
               dims, str, box, es,
               CU_TENSOR_MAP_INTERLEAVE_NONE, CU_TENSOR_MAP_SWIZZLE_128B,
               CU_TENSOR_MAP_L2_PROMOTION_L2_128B,
               CU_TENSOR_MAP_FLOAT_OOB_FILL_NONE) != CUDA_SUCCESS)
            return false;
    }
    {
        cuuint32_t box[2]  = {(cuuint32_t)KT, 128};
        cuuint64_t dims[2] = {F_DIM, (cuuint64_t)P_DIM * Q_DIM};
        cuuint64_t str[1]  = {F_DIM * 4};
        if (fn(tb, CU_TENSOR_MAP_DATA_TYPE_FLOAT32, 2, (void*)W,
               dims, str, box, es,
               CU_TENSOR_MAP_INTERLEAVE_NONE, CU_TENSOR_MAP_SWIZZLE_128B,
               CU_TENSOR_MAP_L2_PROMOTION_L2_128B,
               CU_TENSOR_MAP_FLOAT_OOB_FILL_NONE) != CUDA_SUCCESS)
            return false;
    }
    return true;
}

// ============================================================================
// Launch — identify inputs by element count (robust to metadata ordering)
// ============================================================================
extern "C" void kernel_launch(void* const* d_in, const int* in_sizes, int n_in,
                              void* d_out, int out_size) {
    const float* x        = nullptr;   // 256*2048      = 524288
    const float* W        = nullptr;   // 64*128*2048   = 16777216
    const float* bias     = nullptr;   // 64*128        = 8192
    const void*  part_idx = nullptr;   // 64*1000       = 64000

    for (int i = 0; i < n_in; i++) {
        switch (in_sizes[i]) {
            case 524288:   x        = (const float*)d_in[i]; break;
            case 16777216: W        = (const float*)d_in[i]; break;
            case 8192:     bias     = (const float*)d_in[i]; break;
            case 64000:    part_idx = d_in[i];               break;
            default: break;
        }
    }
    if (!x)        x        = (const float*)d_in[0];
    if (!W)        W        = (const float*)d_in[1];
    if (!bias)     bias     = (const float*)d_in[2];
    if (!part_idx) part_idx = d_in[3];

    float* out = (float*)d_out;

    cudaFuncSetAttribute(cc_kernel_tma,
                         cudaFuncAttributeMaxDynamicSharedMemorySize, SM_TOTAL);
    cudaFuncSetAttribute(cc_kernel_cp,
                         cudaFuncAttributeMaxDynamicSharedMemorySize, SM_TOTAL);

    dim3 grid(B_DIM / M_TILE, P_DIM);    // 4 x 64 = 256 CTAs
    CUtensorMap ta, tb;
    if (make_tensormaps(x, W, &ta, &tb)) {
        cc_kernel_tma<<<grid, THREADS, SM_TOTAL>>>(ta, tb, bias, part_idx, out);
    } else {
        cc_kernel_cp<<<grid, THREADS, SM_TOTAL>>>(x, W, bias, part_idx, out);
    }
}